// round 4
// baseline (speedup 1.0000x reference)
#include <cuda_runtime.h>
#include <cstdint>
#include <cstddef>

#define BB 2
#define NN 512
#define HH 128
#define DD 128
#define TTT 8
#define ZZ 256

#define TR 64
#define TS 32
#define NSP 16          // number of s-chunks (NN/TS)
#define ESTRIDE 132

// ---------------- device scratch (no allocation allowed) ----------------
__device__ __align__(16) float g_m1 [BB*NN*DD];       // z@Wm1 + bm1
__device__ __align__(16) float g_m2f[BB*NN*DD];       // z@Wm2 + bm2 + graph@Wmg + bmg + bme
__device__ __align__(16) float g_o1 [BB*NN*DD];       // z@Wo1 + bo1 + bo2
__device__ __align__(16) float g_t1 [BB*NN*TTT];      // z@Wt1 + bt1
__device__ __align__(16) float g_t2f[BB*NN*TTT];      // z@Wt2 + bt2 + graph@Wtg + btg + bte
__device__ __align__(16) float g_gm [BB*DD];
__device__ __align__(16) float g_gt [BB*TTT];
__device__ __align__(16) float g_part[BB*NSP*NN*DD];  // per-s-chunk partial max (plain stores)

// ---------------- kG: graph projections ----------------
__global__ void FALR3_kG(const float* __restrict__ graph,
                         const float* __restrict__ Wmg, const float* __restrict__ bmg,
                         const float* __restrict__ bme,
                         const float* __restrict__ Wtg, const float* __restrict__ btg,
                         const float* __restrict__ bte) {
    int b = blockIdx.x, t = threadIdx.x;
    __shared__ float g[HH];
    g[t] = graph[b*HH + t];
    __syncthreads();
    float a = 0.f;
#pragma unroll 8
    for (int k = 0; k < HH; k++) a += g[k] * Wmg[k*DD + t];
    g_gm[b*DD + t] = a + bmg[t] + bme[t];
    if (t < TTT) {
        float a2 = 0.f;
#pragma unroll 8
        for (int k = 0; k < HH; k++) a2 += g[k] * Wtg[k*TTT + t];
        g_gt[b*TTT + t] = a2 + btg[t] + bte[t];
    }
}

// ---------------- kA: per-node projections (8 rows/block) ----------------
__global__ void FALR3_kA(const float* __restrict__ node, const float* __restrict__ hidden,
                         const float* __restrict__ Wm1, const float* __restrict__ bm1,
                         const float* __restrict__ Wm2, const float* __restrict__ bm2,
                         const float* __restrict__ Wo1, const float* __restrict__ bo1,
                         const float* __restrict__ bo2,
                         const float* __restrict__ Wt1, const float* __restrict__ bt1,
                         const float* __restrict__ Wt2, const float* __restrict__ bt2) {
    int row0 = blockIdx.x * 8, t = threadIdx.x;
    int b = row0 / NN;
    __shared__ float z[8][ZZ];
#pragma unroll
    for (int r = 0; r < 8; r++) {
        z[r][t]      = node  [(row0 + r)*HH + t];
        z[r][HH + t] = hidden[(row0 + r)*HH + t];
    }
    __syncthreads();
    float a1[8], a2[8], a3[8];
#pragma unroll
    for (int r = 0; r < 8; r++) { a1[r] = 0.f; a2[r] = 0.f; a3[r] = 0.f; }
    for (int k = 0; k < ZZ; k++) {
        float w1 = Wm1[k*DD + t], w2 = Wm2[k*DD + t], w3 = Wo1[k*DD + t];
#pragma unroll
        for (int r = 0; r < 8; r++) {
            float zk = z[r][k];
            a1[r] += zk * w1; a2[r] += zk * w2; a3[r] += zk * w3;
        }
    }
    float gm = g_gm[b*DD + t];
#pragma unroll
    for (int r = 0; r < 8; r++) {
        int row = row0 + r;
        g_m1 [row*DD + t] = a1[r] + bm1[t];
        g_m2f[row*DD + t] = a2[r] + bm2[t] + gm;
        g_o1 [row*DD + t] = a3[r] + bo1[t] + bo2[t];
    }
    if (t < 2*TTT) {
        int tt = t & 7; bool second = (t >= TTT);
        const float* W = second ? Wt2 : Wt1;
        float a[8];
#pragma unroll
        for (int r = 0; r < 8; r++) a[r] = 0.f;
        for (int k = 0; k < ZZ; k++) {
            float w = W[k*TTT + tt];
#pragma unroll
            for (int r = 0; r < 8; r++) a[r] += z[r][k] * w;
        }
        if (!second) {
#pragma unroll
            for (int r = 0; r < 8; r++) g_t1[(row0 + r)*TTT + tt] = a[r] + bt1[tt];
        } else {
            float gt = g_gt[b*TTT + tt];
#pragma unroll
            for (int r = 0; r < 8; r++) g_t2f[(row0 + r)*TTT + tt] = a[r] + bt2[tt] + gt;
        }
    }
}

// ---------------- kB: fused edge GEMM + tri + masked max (partials) --------
// grid (NSP, NN/TR, BB), 256 threads. Static smem ~40.7 KB, all alignas(16).
__global__ __launch_bounds__(256) void FALR3_kB(
        const float* __restrict__ edge, const float* __restrict__ adj,
        const float* __restrict__ Wme,  const float* __restrict__ Wte,
        float* __restrict__ out_tri) {
    __shared__ __align__(16) float Es[TR*ESTRIDE];
    __shared__ __align__(16) float Wts[128*TTT];
    __shared__ __align__(16) float m2s[128];
    __shared__ __align__(16) float t2s[TTT];
    __shared__ __align__(16) float t1s[TR*TTT];
    __shared__ __align__(16) float adjs[TR];

    int tid = threadIdx.x;
    int b = blockIdx.z, r0 = blockIdx.y * TR, s0 = blockIdx.x * TS;
    int tx = tid & 15, ty = tid >> 4;
    int c0 = tx * 4;        // column group 0
    int c1 = 64 + tx * 4;   // column group 1

    for (int i = tid; i < 128*TTT; i += 256) Wts[i] = Wte[i];
    for (int i = tid; i < TR*TTT;  i += 256) t1s[i] = g_t1[(b*NN + r0)*TTT + i];

    float m1r[4][8];
#pragma unroll
    for (int i = 0; i < 4; i++) {
        const float* base = &g_m1[(b*NN + r0 + ty*4 + i)*DD];
        float4 u0 = *(const float4*)&base[c0];
        float4 u1 = *(const float4*)&base[c1];
        m1r[i][0]=u0.x; m1r[i][1]=u0.y; m1r[i][2]=u0.z; m1r[i][3]=u0.w;
        m1r[i][4]=u1.x; m1r[i][5]=u1.y; m1r[i][6]=u1.z; m1r[i][7]=u1.w;
    }
    float mx[4][8];
#pragma unroll
    for (int i = 0; i < 4; i++)
#pragma unroll
        for (int j = 0; j < 8; j++) mx[i][j] = -3.402823466e+38f;

    for (int s = s0; s < s0 + TS; ++s) {
        __syncthreads();   // protect Es/m2s/adjs/t2s from previous iter consumers
        const float4* esrc = (const float4*)(edge + ((size_t)((b*NN + s)*NN + r0)) * HH);
        for (int v = tid; v < TR*32; v += 256) {
            float4 f = esrc[v];
            int row = v >> 5, c = v & 31;
            *(float4*)&Es[row*ESTRIDE + c*4] = f;
        }
        if (tid < 128)               m2s[tid]       = g_m2f[(b*NN + s)*DD + tid];
        else if (tid < 128 + TR)     adjs[tid-128]  = adj[(size_t)(b*NN + s)*NN + r0 + (tid - 128)];
        else if (tid < 128 + TR + 8) t2s[tid-128-TR]= g_t2f[(b*NN + s)*TTT + (tid - 128 - TR)];
        __syncthreads();

        float acc[4][8];
#pragma unroll
        for (int i = 0; i < 4; i++)
#pragma unroll
            for (int j = 0; j < 8; j++) acc[i][j] = 0.f;

        for (int k = 0; k < 128; k += 4) {
            float ef[4][4];
#pragma unroll
            for (int i = 0; i < 4; i++)
#pragma unroll
                for (int kk = 0; kk < 4; kk++)
                    ef[i][kk] = Es[(ty*4 + i)*ESTRIDE + k + kk];
#pragma unroll
            for (int kk = 0; kk < 4; kk++) {
                float4 wa = *(const float4*)&Wme[(k + kk)*128 + c0];
                float4 wb = *(const float4*)&Wme[(k + kk)*128 + c1];
#pragma unroll
                for (int i = 0; i < 4; i++) {
                    float e = ef[i][kk];
                    acc[i][0] += e * wa.x; acc[i][1] += e * wa.y;
                    acc[i][2] += e * wa.z; acc[i][3] += e * wa.w;
                    acc[i][4] += e * wb.x; acc[i][5] += e * wb.y;
                    acc[i][6] += e * wb.z; acc[i][7] += e * wb.w;
                }
            }
        }

        // triplet messages: 64 rows x 8 t; each thread does 2 adjacent t of one row
        {
            int o = tid * 2, row = o >> 3, tt = o & 7;
            const float* er = &Es[row*ESTRIDE];
            float a0 = 0.f, a1 = 0.f;
#pragma unroll 8
            for (int k = 0; k < 128; k++) {
                float e = er[k];
                a0 += e * Wts[k*TTT + tt];
                a1 += e * Wts[k*TTT + tt + 1];
            }
            float v0 = fmaxf(a0 + t1s[row*TTT + tt]     + t2s[tt],     0.f);
            float v1 = fmaxf(a1 + t1s[row*TTT + tt + 1] + t2s[tt + 1], 0.f);
            size_t oix = ((size_t)((b*NN + s)*NN) + r0 + row)*TTT + tt;
            out_tri[oix]     = v0;
            out_tri[oix + 1] = v1;
        }

        // mask by adjacency (multiply, matching reference) + running max over s
        float m2v[8];
#pragma unroll
        for (int j = 0; j < 4; j++) { m2v[j] = m2s[c0 + j]; m2v[4 + j] = m2s[c1 + j]; }
#pragma unroll
        for (int i = 0; i < 4; i++) {
            float ad = adjs[ty*4 + i];
#pragma unroll
            for (int j = 0; j < 8; j++) {
                float v = (acc[i][j] + m1r[i][j] + m2v[j]) * ad;
                mx[i][j] = fmaxf(mx[i][j], v);
            }
        }
    }

    // plain stores of the block-local max tile (no atomics, no sentinel deps)
    float* pbase = &g_part[((size_t)(b*NSP + blockIdx.x)*NN + r0)*DD];
#pragma unroll
    for (int i = 0; i < 4; i++) {
        float* dst = pbase + (ty*4 + i)*DD;
#pragma unroll
        for (int j = 0; j < 4; j++) {
            dst[c0 + j] = mx[i][j];
            dst[c1 + j] = mx[i][4 + j];
        }
    }
}

// ---------------- kC: reduce partials, ret = o1f + msgs@Wo2 ----------------
__global__ void FALR3_kC(const float* __restrict__ Wo2, float* __restrict__ out) {
    int row0 = blockIdx.x * 8, t = threadIdx.x;
    int b = row0 / NN;
    int rn0 = row0 - b*NN;
    __shared__ float ms[8][DD];
#pragma unroll
    for (int r = 0; r < 8; r++) {
        float m = -3.402823466e+38f;
#pragma unroll
        for (int p = 0; p < NSP; p++)
            m = fmaxf(m, g_part[((size_t)(b*NSP + p)*NN + rn0 + r)*DD + t]);
        ms[r][t] = m;
    }
    __syncthreads();
    float acc[8];
#pragma unroll
    for (int r = 0; r < 8; r++) acc[r] = 0.f;
    for (int k = 0; k < DD; k++) {
        float w = Wo2[k*DD + t];
#pragma unroll
        for (int r = 0; r < 8; r++) acc[r] += ms[r][k] * w;
    }
#pragma unroll
    for (int r = 0; r < 8; r++)
        out[(row0 + r)*DD + t] = acc[r] + g_o1[(row0 + r)*DD + t];
}

// ---------------- launch ----------------
extern "C" void kernel_launch(void* const* d_in, const int* in_sizes, int n_in,
                              void* d_out, int out_size) {
    const float* node  = (const float*)d_in[0];
    const float* edge  = (const float*)d_in[1];
    const float* graph = (const float*)d_in[2];
    const float* adj   = (const float*)d_in[3];
    const float* hidden= (const float*)d_in[4];
    const float* Wm1 = (const float*)d_in[5];  const float* bm1 = (const float*)d_in[6];
    const float* Wm2 = (const float*)d_in[7];  const float* bm2 = (const float*)d_in[8];
    const float* Wme = (const float*)d_in[9];  const float* bme = (const float*)d_in[10];
    const float* Wmg = (const float*)d_in[11]; const float* bmg = (const float*)d_in[12];
    const float* Wo1 = (const float*)d_in[13]; const float* bo1 = (const float*)d_in[14];
    const float* Wo2 = (const float*)d_in[15]; const float* bo2 = (const float*)d_in[16];
    const float* Wt1 = (const float*)d_in[17]; const float* bt1 = (const float*)d_in[18];
    const float* Wt2 = (const float*)d_in[19]; const float* bt2 = (const float*)d_in[20];
    const float* Wte = (const float*)d_in[21]; const float* bte = (const float*)d_in[22];
    const float* Wtg = (const float*)d_in[23]; const float* btg = (const float*)d_in[24];

    float* out     = (float*)d_out;
    float* out_ret = out;                       // [B,N,D]
    float* out_tri = out + BB*NN*DD;            // [B,N,N,T]

    FALR3_kG<<<BB, 128>>>(graph, Wmg, bmg, bme, Wtg, btg, bte);
    FALR3_kA<<<BB*NN/8, 128>>>(node, hidden, Wm1, bm1, Wm2, bm2,
                               Wo1, bo1, bo2, Wt1, bt1, Wt2, bt2);

    dim3 gB(NSP, NN/TR, BB);   // (16, 8, 2) = 256 blocks
    FALR3_kB<<<gB, 256>>>(edge, adj, Wme, Wte, out_tri);

    FALR3_kC<<<BB*NN/8, 128>>>(Wo2, out_ret);
}

// round 5
// speedup vs baseline: 1.0444x; 1.0444x over previous
#include <cuda_runtime.h>
#include <cstdint>
#include <cstddef>

#define BB 2
#define NN 512
#define HH 128
#define DD 128
#define TTT 8
#define ZZ 256

#define TR 64
#define TS 32
#define NSP 16          // number of s-chunks (NN/TS)
#define ESTRIDE 132

// ---------------- packed f32x2 helpers ----------------
__device__ __forceinline__ unsigned long long pack2(float x, float y) {
    unsigned long long r;
    asm("mov.b64 %0, {%1, %2};" : "=l"(r) : "f"(x), "f"(y));
    return r;
}
__device__ __forceinline__ float2 unpack2(unsigned long long v) {
    float2 r;
    asm("mov.b64 {%0, %1}, %2;" : "=f"(r.x), "=f"(r.y) : "l"(v));
    return r;
}
__device__ __forceinline__ void fma2(unsigned long long& d,
                                     unsigned long long a, unsigned long long b) {
    asm("fma.rn.f32x2 %0, %1, %2, %3;" : "=l"(d) : "l"(a), "l"(b), "l"(d));
}

// ---------------- device scratch (no allocation allowed) ----------------
__device__ __align__(16) float g_m1 [BB*NN*DD];       // z@Wm1 + bm1
__device__ __align__(16) float g_m2f[BB*NN*DD];       // z@Wm2 + bm2 + graph@Wmg + bmg + bme
__device__ __align__(16) float g_o1 [BB*NN*DD];       // z@Wo1 + bo1 + bo2
__device__ __align__(16) float g_t1 [BB*NN*TTT];      // z@Wt1 + bt1
__device__ __align__(16) float g_t2f[BB*NN*TTT];      // z@Wt2 + bt2 + graph@Wtg + btg + bte
__device__ __align__(16) float g_gm [BB*DD];
__device__ __align__(16) float g_gt [BB*TTT];
__device__ __align__(16) float g_part[BB*NSP*NN*DD];  // per-s-chunk partial max (plain stores)

// ---------------- kG: graph projections ----------------
__global__ void FALR3_kG(const float* __restrict__ graph,
                         const float* __restrict__ Wmg, const float* __restrict__ bmg,
                         const float* __restrict__ bme,
                         const float* __restrict__ Wtg, const float* __restrict__ btg,
                         const float* __restrict__ bte) {
    int b = blockIdx.x, t = threadIdx.x;
    __shared__ float g[HH];
    g[t] = graph[b*HH + t];
    __syncthreads();
    float a = 0.f;
#pragma unroll 8
    for (int k = 0; k < HH; k++) a += g[k] * Wmg[k*DD + t];
    g_gm[b*DD + t] = a + bmg[t] + bme[t];
    if (t < TTT) {
        float a2 = 0.f;
#pragma unroll 8
        for (int k = 0; k < HH; k++) a2 += g[k] * Wtg[k*TTT + t];
        g_gt[b*TTT + t] = a2 + btg[t] + bte[t];
    }
}

// ---------------- kA: per-node projections (8 rows/block) ----------------
__global__ void FALR3_kA(const float* __restrict__ node, const float* __restrict__ hidden,
                         const float* __restrict__ Wm1, const float* __restrict__ bm1,
                         const float* __restrict__ Wm2, const float* __restrict__ bm2,
                         const float* __restrict__ Wo1, const float* __restrict__ bo1,
                         const float* __restrict__ bo2,
                         const float* __restrict__ Wt1, const float* __restrict__ bt1,
                         const float* __restrict__ Wt2, const float* __restrict__ bt2) {
    int row0 = blockIdx.x * 8, t = threadIdx.x;
    int b = row0 / NN;
    __shared__ float z[8][ZZ];
#pragma unroll
    for (int r = 0; r < 8; r++) {
        z[r][t]      = node  [(row0 + r)*HH + t];
        z[r][HH + t] = hidden[(row0 + r)*HH + t];
    }
    __syncthreads();
    float a1[8], a2[8], a3[8];
#pragma unroll
    for (int r = 0; r < 8; r++) { a1[r] = 0.f; a2[r] = 0.f; a3[r] = 0.f; }
    for (int k = 0; k < ZZ; k++) {
        float w1 = Wm1[k*DD + t], w2 = Wm2[k*DD + t], w3 = Wo1[k*DD + t];
#pragma unroll
        for (int r = 0; r < 8; r++) {
            float zk = z[r][k];
            a1[r] += zk * w1; a2[r] += zk * w2; a3[r] += zk * w3;
        }
    }
    float gm = g_gm[b*DD + t];
#pragma unroll
    for (int r = 0; r < 8; r++) {
        int row = row0 + r;
        g_m1 [row*DD + t] = a1[r] + bm1[t];
        g_m2f[row*DD + t] = a2[r] + bm2[t] + gm;
        g_o1 [row*DD + t] = a3[r] + bo1[t] + bo2[t];
    }
    if (t < 2*TTT) {
        int tt = t & 7; bool second = (t >= TTT);
        const float* W = second ? Wt2 : Wt1;
        float a[8];
#pragma unroll
        for (int r = 0; r < 8; r++) a[r] = 0.f;
        for (int k = 0; k < ZZ; k++) {
            float w = W[k*TTT + tt];
#pragma unroll
            for (int r = 0; r < 8; r++) a[r] += z[r][k] * w;
        }
        if (!second) {
#pragma unroll
            for (int r = 0; r < 8; r++) g_t1[(row0 + r)*TTT + tt] = a[r] + bt1[tt];
        } else {
            float gt = g_gt[b*TTT + tt];
#pragma unroll
            for (int r = 0; r < 8; r++) g_t2f[(row0 + r)*TTT + tt] = a[r] + bt2[tt] + gt;
        }
    }
}

// ---------------- kB: fused edge GEMM + tri + masked max (partials) --------
// grid (NSP, NN/TR, BB), 256 threads. Static smem ~40.7 KB. Packed f32x2 math.
__global__ __launch_bounds__(256) void FALR3_kB(
        const float* __restrict__ edge, const float* __restrict__ adj,
        const float* __restrict__ Wme,  const float* __restrict__ Wte,
        float* __restrict__ out_tri) {
    __shared__ __align__(16) float Es[TR*ESTRIDE];
    __shared__ __align__(16) float Wts[128*TTT];
    __shared__ __align__(16) float m2s[128];
    __shared__ __align__(16) float t2s[TTT];
    __shared__ __align__(16) float t1s[TR*TTT];
    __shared__ __align__(16) float adjs[TR];

    int tid = threadIdx.x;
    int b = blockIdx.z, r0 = blockIdx.y * TR, s0 = blockIdx.x * TS;
    int tx = tid & 15, ty = tid >> 4;
    int c0 = tx * 4;        // column group 0
    int c1 = 64 + tx * 4;   // column group 1

    for (int i = tid; i < 128*TTT; i += 256) Wts[i] = Wte[i];
    for (int i = tid; i < TR*TTT;  i += 256) t1s[i] = g_t1[(b*NN + r0)*TTT + i];

    float m1r[4][8];
#pragma unroll
    for (int i = 0; i < 4; i++) {
        const float* base = &g_m1[(b*NN + r0 + ty*4 + i)*DD];
        float4 u0 = *(const float4*)&base[c0];
        float4 u1 = *(const float4*)&base[c1];
        m1r[i][0]=u0.x; m1r[i][1]=u0.y; m1r[i][2]=u0.z; m1r[i][3]=u0.w;
        m1r[i][4]=u1.x; m1r[i][5]=u1.y; m1r[i][6]=u1.z; m1r[i][7]=u1.w;
    }
    float mx[4][8];
#pragma unroll
    for (int i = 0; i < 4; i++)
#pragma unroll
        for (int j = 0; j < 8; j++) mx[i][j] = -3.402823466e+38f;

    for (int s = s0; s < s0 + TS; ++s) {
        __syncthreads();   // protect Es/m2s/adjs/t2s from previous iter consumers
        const float4* esrc = (const float4*)(edge + ((size_t)((b*NN + s)*NN + r0)) * HH);
        for (int v = tid; v < TR*32; v += 256) {
            float4 f = esrc[v];
            int row = v >> 5, c = v & 31;
            *(float4*)&Es[row*ESTRIDE + c*4] = f;
        }
        if (tid < 128)               m2s[tid]       = g_m2f[(b*NN + s)*DD + tid];
        else if (tid < 128 + TR)     adjs[tid-128]  = adj[(size_t)(b*NN + s)*NN + r0 + (tid - 128)];
        else if (tid < 128 + TR + 8) t2s[tid-128-TR]= g_t2f[(b*NN + s)*TTT + (tid - 128 - TR)];
        __syncthreads();

        // packed accumulators: acc2[i][p] = pair (d = 2p, 2p+1) of column group
        unsigned long long acc2[4][4];
#pragma unroll
        for (int i = 0; i < 4; i++)
#pragma unroll
            for (int p = 0; p < 4; p++) acc2[i][p] = 0ULL;

        for (int k = 0; k < 128; k += 4) {
            float2 ef2[4][2];
#pragma unroll
            for (int i = 0; i < 4; i++) {
                ef2[i][0] = *(const float2*)&Es[(ty*4 + i)*ESTRIDE + k];
                ef2[i][1] = *(const float2*)&Es[(ty*4 + i)*ESTRIDE + k + 2];
            }
#pragma unroll
            for (int kk = 0; kk < 4; kk++) {
                // longlong2 load: 16B, yields two packed f32 pairs (w[c], w[c+1]) etc.
                longlong2 wa = *(const longlong2*)&Wme[(k + kk)*128 + c0];
                longlong2 wb = *(const longlong2*)&Wme[(k + kk)*128 + c1];
#pragma unroll
                for (int i = 0; i < 4; i++) {
                    float e = (kk < 2) ? ((kk == 0) ? ef2[i][0].x : ef2[i][0].y)
                                       : ((kk == 2) ? ef2[i][1].x : ef2[i][1].y);
                    unsigned long long e2 = pack2(e, e);
                    fma2(acc2[i][0], e2, (unsigned long long)wa.x);
                    fma2(acc2[i][1], e2, (unsigned long long)wa.y);
                    fma2(acc2[i][2], e2, (unsigned long long)wb.x);
                    fma2(acc2[i][3], e2, (unsigned long long)wb.y);
                }
            }
        }

        // triplet messages: 64 rows x 8 t; each thread does 2 adjacent t of one row
        {
            int o = tid * 2, row = o >> 3, tt = o & 7;
            const float* er = &Es[row*ESTRIDE];
            unsigned long long a2 = 0ULL;
#pragma unroll 8
            for (int k = 0; k < 128; k++) {
                float e = er[k];
                unsigned long long e2 = pack2(e, e);
                unsigned long long w2 = *(const unsigned long long*)&Wts[k*TTT + tt];
                fma2(a2, e2, w2);
            }
            float2 a = unpack2(a2);
            float v0 = fmaxf(a.x + t1s[row*TTT + tt]     + t2s[tt],     0.f);
            float v1 = fmaxf(a.y + t1s[row*TTT + tt + 1] + t2s[tt + 1], 0.f);
            size_t oix = ((size_t)((b*NN + s)*NN) + r0 + row)*TTT + tt;
            out_tri[oix]     = v0;
            out_tri[oix + 1] = v1;
        }

        // mask by adjacency (multiply, matching reference) + running max over s
        float m2v[8];
#pragma unroll
        for (int j = 0; j < 4; j++) { m2v[j] = m2s[c0 + j]; m2v[4 + j] = m2s[c1 + j]; }
#pragma unroll
        for (int i = 0; i < 4; i++) {
            float ad = adjs[ty*4 + i];
#pragma unroll
            for (int p = 0; p < 4; p++) {
                float2 av = unpack2(acc2[i][p]);
                float va = (av.x + m1r[i][2*p]     + m2v[2*p])     * ad;
                float vb = (av.y + m1r[i][2*p + 1] + m2v[2*p + 1]) * ad;
                mx[i][2*p]     = fmaxf(mx[i][2*p],     va);
                mx[i][2*p + 1] = fmaxf(mx[i][2*p + 1], vb);
            }
        }
    }

    // plain stores of the block-local max tile (no atomics, no sentinel deps)
    float* pbase = &g_part[((size_t)(b*NSP + blockIdx.x)*NN + r0)*DD];
#pragma unroll
    for (int i = 0; i < 4; i++) {
        float* dst = pbase + (ty*4 + i)*DD;
#pragma unroll
        for (int j = 0; j < 4; j++) {
            dst[c0 + j] = mx[i][j];
            dst[c1 + j] = mx[i][4 + j];
        }
    }
}

// ---------------- kC: reduce partials, ret = o1f + msgs@Wo2 ----------------
// 2 rows per block -> 512 blocks for better occupancy/latency hiding.
__global__ void FALR3_kC(const float* __restrict__ Wo2, float* __restrict__ out) {
    int row0 = blockIdx.x * 2, t = threadIdx.x;
    int b = row0 / NN;
    int rn0 = row0 - b*NN;
    __shared__ float ms[2][DD];
#pragma unroll
    for (int r = 0; r < 2; r++) {
        float m = -3.402823466e+38f;
#pragma unroll
        for (int p = 0; p < NSP; p++)
            m = fmaxf(m, g_part[((size_t)(b*NSP + p)*NN + rn0 + r)*DD + t]);
        ms[r][t] = m;
    }
    __syncthreads();
    float acc0 = 0.f, acc1 = 0.f;
    for (int k = 0; k < DD; k++) {
        float w = Wo2[k*DD + t];
        acc0 += ms[0][k] * w;
        acc1 += ms[1][k] * w;
    }
    out[(row0 + 0)*DD + t] = acc0 + g_o1[(row0 + 0)*DD + t];
    out[(row0 + 1)*DD + t] = acc1 + g_o1[(row0 + 1)*DD + t];
}

// ---------------- launch ----------------
extern "C" void kernel_launch(void* const* d_in, const int* in_sizes, int n_in,
                              void* d_out, int out_size) {
    const float* node  = (const float*)d_in[0];
    const float* edge  = (const float*)d_in[1];
    const float* graph = (const float*)d_in[2];
    const float* adj   = (const float*)d_in[3];
    const float* hidden= (const float*)d_in[4];
    const float* Wm1 = (const float*)d_in[5];  const float* bm1 = (const float*)d_in[6];
    const float* Wm2 = (const float*)d_in[7];  const float* bm2 = (const float*)d_in[8];
    const float* Wme = (const float*)d_in[9];  const float* bme = (const float*)d_in[10];
    const float* Wmg = (const float*)d_in[11]; const float* bmg = (const float*)d_in[12];
    const float* Wo1 = (const float*)d_in[13]; const float* bo1 = (const float*)d_in[14];
    const float* Wo2 = (const float*)d_in[15]; const float* bo2 = (const float*)d_in[16];
    const float* Wt1 = (const float*)d_in[17]; const float* bt1 = (const float*)d_in[18];
    const float* Wt2 = (const float*)d_in[19]; const float* bt2 = (const float*)d_in[20];
    const float* Wte = (const float*)d_in[21]; const float* bte = (const float*)d_in[22];
    const float* Wtg = (const float*)d_in[23]; const float* btg = (const float*)d_in[24];

    float* out     = (float*)d_out;
    float* out_ret = out;                       // [B,N,D]
    float* out_tri = out + BB*NN*DD;            // [B,N,N,T]

    FALR3_kG<<<BB, 128>>>(graph, Wmg, bmg, bme, Wtg, btg, bte);
    FALR3_kA<<<BB*NN/8, 128>>>(node, hidden, Wm1, bm1, Wm2, bm2,
                               Wo1, bo1, bo2, Wt1, bt1, Wt2, bt2);

    dim3 gB(NSP, NN/TR, BB);   // (16, 8, 2) = 256 blocks
    FALR3_kB<<<gB, 256>>>(edge, adj, Wme, Wte, out_tri);

    FALR3_kC<<<BB*NN/2, 128>>>(Wo2, out_ret);
}

// round 6
// speedup vs baseline: 1.3172x; 1.2611x over previous
#include <cuda_runtime.h>
#include <cstdint>
#include <cstddef>

#define BB 2
#define NN 512
#define HH 128
#define DD 128
#define TTT 8
#define ZZ 256

#define TR 64
#define TS 32
#define NSP 16          // number of s-chunks (NN/TS)
#define ESTRIDE 132
#define FLT_MAX_F 3.402823466e+38f

typedef unsigned long long ull;

// ---------------- packed f32x2 helpers ----------------
__device__ __forceinline__ ull pack2(float x, float y) {
    ull r;
    asm("mov.b64 %0, {%1, %2};" : "=l"(r) : "f"(x), "f"(y));
    return r;
}
__device__ __forceinline__ float2 unpack2(ull v) {
    float2 r;
    asm("mov.b64 {%0, %1}, %2;" : "=f"(r.x), "=f"(r.y) : "l"(v));
    return r;
}
__device__ __forceinline__ void fma2(ull& d, ull a, ull b) {
    asm("fma.rn.f32x2 %0, %1, %2, %3;" : "=l"(d) : "l"(a), "l"(b), "l"(d));
}

// ---------------- device scratch (no allocation allowed) ----------------
__device__ __align__(16) float g_m1 [BB*NN*DD];       // z@Wm1 + bm1
__device__ __align__(16) float g_m2f[BB*NN*DD];       // z@Wm2 + bm2 + graph@Wmg + bmg + bme
__device__ __align__(16) float g_o1 [BB*NN*DD];       // z@Wo1 + bo1 + bo2
__device__ __align__(16) float g_t1 [BB*NN*TTT];      // z@Wt1 + bt1
__device__ __align__(16) float g_t2f[BB*NN*TTT];      // z@Wt2 + bt2 + graph@Wtg + btg + bte
__device__ __align__(16) float g_gm [BB*DD];
__device__ __align__(16) float g_gt [BB*TTT];
__device__ __align__(16) float g_part[BB*NSP*NN*DD];  // per-s-chunk partial max (plain stores)

// ---------------- kG: graph projections ----------------
__global__ void FALR3_kG(const float* __restrict__ graph,
                         const float* __restrict__ Wmg, const float* __restrict__ bmg,
                         const float* __restrict__ bme,
                         const float* __restrict__ Wtg, const float* __restrict__ btg,
                         const float* __restrict__ bte) {
    int b = blockIdx.x, t = threadIdx.x;
    __shared__ float g[HH];
    g[t] = graph[b*HH + t];
    __syncthreads();
    float a = 0.f;
#pragma unroll 8
    for (int k = 0; k < HH; k++) a += g[k] * Wmg[k*DD + t];
    g_gm[b*DD + t] = a + bmg[t] + bme[t];
    if (t < TTT) {
        float a2 = 0.f;
#pragma unroll 8
        for (int k = 0; k < HH; k++) a2 += g[k] * Wtg[k*TTT + t];
        g_gt[b*TTT + t] = a2 + btg[t] + bte[t];
    }
}

// ---------------- kA: per-node projections (8 rows/block) ----------------
__global__ void FALR3_kA(const float* __restrict__ node, const float* __restrict__ hidden,
                         const float* __restrict__ Wm1, const float* __restrict__ bm1,
                         const float* __restrict__ Wm2, const float* __restrict__ bm2,
                         const float* __restrict__ Wo1, const float* __restrict__ bo1,
                         const float* __restrict__ bo2,
                         const float* __restrict__ Wt1, const float* __restrict__ bt1,
                         const float* __restrict__ Wt2, const float* __restrict__ bt2) {
    int row0 = blockIdx.x * 8, t = threadIdx.x;
    int b = row0 / NN;
    __shared__ float z[8][ZZ];
#pragma unroll
    for (int r = 0; r < 8; r++) {
        z[r][t]      = node  [(row0 + r)*HH + t];
        z[r][HH + t] = hidden[(row0 + r)*HH + t];
    }
    __syncthreads();
    float a1[8], a2[8], a3[8];
#pragma unroll
    for (int r = 0; r < 8; r++) { a1[r] = 0.f; a2[r] = 0.f; a3[r] = 0.f; }
    for (int k = 0; k < ZZ; k++) {
        float w1 = Wm1[k*DD + t], w2 = Wm2[k*DD + t], w3 = Wo1[k*DD + t];
#pragma unroll
        for (int r = 0; r < 8; r++) {
            float zk = z[r][k];
            a1[r] += zk * w1; a2[r] += zk * w2; a3[r] += zk * w3;
        }
    }
    float gm = g_gm[b*DD + t];
#pragma unroll
    for (int r = 0; r < 8; r++) {
        int row = row0 + r;
        g_m1 [row*DD + t] = a1[r] + bm1[t];
        g_m2f[row*DD + t] = a2[r] + bm2[t] + gm;
        g_o1 [row*DD + t] = a3[r] + bo1[t] + bo2[t];
    }
    if (t < 2*TTT) {
        int tt = t & 7; bool second = (t >= TTT);
        const float* W = second ? Wt2 : Wt1;
        float a[8];
#pragma unroll
        for (int r = 0; r < 8; r++) a[r] = 0.f;
        for (int k = 0; k < ZZ; k++) {
            float w = W[k*TTT + tt];
#pragma unroll
            for (int r = 0; r < 8; r++) a[r] += z[r][k] * w;
        }
        if (!second) {
#pragma unroll
            for (int r = 0; r < 8; r++) g_t1[(row0 + r)*TTT + tt] = a[r] + bt1[tt];
        } else {
            float gt = g_gt[b*TTT + tt];
#pragma unroll
            for (int r = 0; r < 8; r++) g_t2f[(row0 + r)*TTT + tt] = a[r] + bt2[tt] + gt;
        }
    }
}

// ---------------- kB: fused edge GEMM + tri + masked max (partials) --------
// grid (NSP, NN/TR, BB), 256 threads, 2 CTAs/SM.
// Thread map: tx = tid&31 -> cols tx*4..tx*4+3 ; ty = tid>>5 -> rows ty*8..ty*8+7.
// adj in {0,1} exactly -> masked max decomposes: mx = max(m1 + A, anyZero?0:-inf)
// with A = max over {s: ad=1} of (acc_s + m2_s); m1 applied once at block end.
__global__ __launch_bounds__(256, 2) void FALR3_kB(
        const float* __restrict__ edge, const float* __restrict__ adj,
        const float* __restrict__ Wme,  const float* __restrict__ Wte,
        float* __restrict__ out_tri) {
    __shared__ __align__(16) float Es[TR*ESTRIDE];       // 33.8 KB
    __shared__ __align__(16) ull   Wp[4*130];            // tri weight pairs, padded
    __shared__ __align__(16) float m2s[128];
    __shared__ __align__(16) float t2s[TTT];
    __shared__ __align__(16) float t1s[TR*TTT];
    __shared__ __align__(16) float adjs[TR];

    int tid = threadIdx.x;
    int b = blockIdx.z, r0 = blockIdx.y * TR, s0 = blockIdx.x * TS;
    int tx = tid & 31, ty = tid >> 5;
    int col = tx * 4;

    // fill transposed tri-weight pair table: Wp[p*130 + k] = (Wte[k][2p], Wte[k][2p+1])
    {
        int e0 = tid * 2;
#pragma unroll
        for (int u = 0; u < 2; u++) {
            int e = e0 + u;
            int p = e >> 7, k = e & 127;
            Wp[p*130 + k] = pack2(Wte[k*TTT + 2*p], Wte[k*TTT + 2*p + 1]);
        }
    }
    for (int i = tid; i < TR*TTT; i += 256) t1s[i] = g_t1[(b*NN + r0)*TTT + i];

    // loop-carried state
    ull   acc2[8][2];
    float A[8][4];
    float Zr[8];
#pragma unroll
    for (int i = 0; i < 8; i++) {
        Zr[i] = -FLT_MAX_F;
#pragma unroll
        for (int j = 0; j < 4; j++) A[i][j] = -FLT_MAX_F;
    }

    for (int s = s0; s < s0 + TS; ++s) {
        __syncthreads();   // protect Es/m2s/adjs/t2s from previous iter consumers
        const float4* esrc = (const float4*)(edge + ((size_t)((b*NN + s)*NN + r0)) * HH);
        for (int v = tid; v < TR*32; v += 256) {
            float4 f = esrc[v];
            int row = v >> 5, c = v & 31;
            *(float4*)&Es[row*ESTRIDE + c*4] = f;
        }
        if (tid < 128)               m2s[tid]       = g_m2f[(b*NN + s)*DD + tid];
        else if (tid < 128 + TR)     adjs[tid-128]  = adj[(size_t)(b*NN + s)*NN + r0 + (tid - 128)];
        else if (tid < 128 + TR + 8) t2s[tid-128-TR]= g_t2f[(b*NN + s)*TTT + (tid - 128 - TR)];
        __syncthreads();

#pragma unroll
        for (int i = 0; i < 8; i++) { acc2[i][0] = 0ULL; acc2[i][1] = 0ULL; }

        for (int k = 0; k < 128; k += 4) {
            float4 er[8];
#pragma unroll
            for (int i = 0; i < 8; i++)
                er[i] = *(const float4*)&Es[(ty*8 + i)*ESTRIDE + k];
#pragma unroll
            for (int kk = 0; kk < 4; kk++) {
                longlong2 wv = *(const longlong2*)&Wme[(k + kk)*128 + col];
                ull w0 = (ull)wv.x, w1 = (ull)wv.y;
#pragma unroll
                for (int i = 0; i < 8; i++) {
                    float e = (&er[i].x)[kk];
                    ull e2 = pack2(e, e);
                    fma2(acc2[i][0], e2, w0);
                    fma2(acc2[i][1], e2, w1);
                }
            }
        }

        // triplet messages: 256 threads = 64 rows x 4 tt-pairs
        {
            int row = tid >> 2, p = tid & 3, tt = p * 2;
            const float* er = &Es[row*ESTRIDE];
            const ull* wp = &Wp[p*130];
            ull a2 = 0ULL;
#pragma unroll 8
            for (int k = 0; k < 128; k += 4) {
                float4 e4 = *(const float4*)&er[k];
                ull wp0 = wp[k], wp1 = wp[k+1], wp2 = wp[k+2], wp3 = wp[k+3];
                fma2(a2, pack2(e4.x, e4.x), wp0);
                fma2(a2, pack2(e4.y, e4.y), wp1);
                fma2(a2, pack2(e4.z, e4.z), wp2);
                fma2(a2, pack2(e4.w, e4.w), wp3);
            }
            float2 a = unpack2(a2);
            float v0 = fmaxf(a.x + t1s[row*TTT + tt]     + t2s[tt],     0.f);
            float v1 = fmaxf(a.y + t1s[row*TTT + tt + 1] + t2s[tt + 1], 0.f);
            *(float2*)&out_tri[((size_t)((b*NN + s)*NN) + r0 + row)*TTT + tt] =
                make_float2(v0, v1);
        }

        // masked running max (m1 deferred to block end)
        float4 m2v = *(const float4*)&m2s[col];
#pragma unroll
        for (int i = 0; i < 8; i++) {
            float ad = adjs[ty*8 + i];
            bool on = (ad != 0.f);
            if (!on) Zr[i] = 0.f;
            float2 a0 = unpack2(acc2[i][0]);
            float2 a1 = unpack2(acc2[i][1]);
            float t0 = a0.x + m2v.x, t1 = a0.y + m2v.y;
            float t2 = a1.x + m2v.z, t3 = a1.y + m2v.w;
            A[i][0] = fmaxf(A[i][0], on ? t0 : -FLT_MAX_F);
            A[i][1] = fmaxf(A[i][1], on ? t1 : -FLT_MAX_F);
            A[i][2] = fmaxf(A[i][2], on ? t2 : -FLT_MAX_F);
            A[i][3] = fmaxf(A[i][3], on ? t3 : -FLT_MAX_F);
        }
    }

    // block end: fold in m1, combine with zero-presence, store partial tile
    float* pbase = &g_part[((size_t)(b*NSP + blockIdx.x)*NN + r0)*DD];
#pragma unroll
    for (int i = 0; i < 8; i++) {
        int row = ty*8 + i;
        float4 m1v = *(const float4*)&g_m1[(b*NN + r0 + row)*DD + col];
        float z = Zr[i];
        float4 outv;
        outv.x = fmaxf(A[i][0] + m1v.x, z);
        outv.y = fmaxf(A[i][1] + m1v.y, z);
        outv.z = fmaxf(A[i][2] + m1v.z, z);
        outv.w = fmaxf(A[i][3] + m1v.w, z);
        *(float4*)&pbase[row*DD + col] = outv;
    }
}

// ---------------- kC: reduce partials, ret = o1f + msgs@Wo2 ----------------
__global__ void FALR3_kC(const float* __restrict__ Wo2, float* __restrict__ out) {
    int row0 = blockIdx.x * 2, t = threadIdx.x;
    int b = row0 / NN;
    int rn0 = row0 - b*NN;
    __shared__ float ms[2][DD];
#pragma unroll
    for (int r = 0; r < 2; r++) {
        float m = -FLT_MAX_F;
#pragma unroll
        for (int p = 0; p < NSP; p++)
            m = fmaxf(m, g_part[((size_t)(b*NSP + p)*NN + rn0 + r)*DD + t]);
        ms[r][t] = m;
    }
    __syncthreads();
    float acc0 = 0.f, acc1 = 0.f;
    for (int k = 0; k < DD; k++) {
        float w = Wo2[k*DD + t];
        acc0 += ms[0][k] * w;
        acc1 += ms[1][k] * w;
    }
    out[(row0 + 0)*DD + t] = acc0 + g_o1[(row0 + 0)*DD + t];
    out[(row0 + 1)*DD + t] = acc1 + g_o1[(row0 + 1)*DD + t];
}

// ---------------- launch ----------------
extern "C" void kernel_launch(void* const* d_in, const int* in_sizes, int n_in,
                              void* d_out, int out_size) {
    const float* node  = (const float*)d_in[0];
    const float* edge  = (const float*)d_in[1];
    const float* graph = (const float*)d_in[2];
    const float* adj   = (const float*)d_in[3];
    const float* hidden= (const float*)d_in[4];
    const float* Wm1 = (const float*)d_in[5];  const float* bm1 = (const float*)d_in[6];
    const float* Wm2 = (const float*)d_in[7];  const float* bm2 = (const float*)d_in[8];
    const float* Wme = (const float*)d_in[9];  const float* bme = (const float*)d_in[10];
    const float* Wmg = (const float*)d_in[11]; const float* bmg = (const float*)d_in[12];
    const float* Wo1 = (const float*)d_in[13]; const float* bo1 = (const float*)d_in[14];
    const float* Wo2 = (const float*)d_in[15]; const float* bo2 = (const float*)d_in[16];
    const float* Wt1 = (const float*)d_in[17]; const float* bt1 = (const float*)d_in[18];
    const float* Wt2 = (const float*)d_in[19]; const float* bt2 = (const float*)d_in[20];
    const float* Wte = (const float*)d_in[21]; const float* bte = (const float*)d_in[22];
    const float* Wtg = (const float*)d_in[23]; const float* btg = (const float*)d_in[24];

    float* out     = (float*)d_out;
    float* out_ret = out;                       // [B,N,D]
    float* out_tri = out + BB*NN*DD;            // [B,N,N,T]

    FALR3_kG<<<BB, 128>>>(graph, Wmg, bmg, bme, Wtg, btg, bte);
    FALR3_kA<<<BB*NN/8, 128>>>(node, hidden, Wm1, bm1, Wm2, bm2,
                               Wo1, bo1, bo2, Wt1, bt1, Wt2, bt2);

    dim3 gB(NSP, NN/TR, BB);   // (16, 8, 2) = 256 blocks
    FALR3_kB<<<gB, 256>>>(edge, adj, Wme, Wte, out_tri);

    FALR3_kC<<<BB*NN/2, 128>>>(Wo2, out_ret);
}